// round 15
// baseline (speedup 1.0000x reference)
#include <cuda_runtime.h>
#include <cuda_fp16.h>
#include <math.h>
#include <stdint.h>

#define D_MODEL 2048
#define NH      16
#define NKV     4
#define HD      128
#define KV_DIM  512
#define QKVW    3072
#define NB      4
#define SEQ     2048
#define TOKENS  (NB * SEQ)
#define KDIM    2048

// Scratch (device globals — no runtime allocation)
__device__ __half g_qkv  [(size_t)TOKENS * QKVW];
__device__ __half g_attn [(size_t)TOKENS * D_MODEL];
__device__ __half g_xc   [(size_t)TOKENS * D_MODEL];
__device__ __half g_wqkvT[(size_t)QKVW   * D_MODEL];
__device__ __half g_woutT[(size_t)D_MODEL* D_MODEL];

// ---------------------------------------------------------------------------
// Helpers
// ---------------------------------------------------------------------------
__device__ __forceinline__ uint32_t smem_u32(const void* p) {
    uint32_t r;
    asm("{ .reg .u64 t; cvta.to.shared.u64 t, %1; cvt.u32.u64 %0, t; }" : "=r"(r) : "l"(p));
    return r;
}
__device__ __forceinline__ void cp16(uint32_t d, const void* s) {
    asm volatile("cp.async.cg.shared.global [%0], [%1], 16;" :: "r"(d), "l"(s));
}
__device__ __forceinline__ void cp_commit() {
    asm volatile("cp.async.commit_group;" ::: "memory");
}
template<int N> __device__ __forceinline__ void cp_wait() {
    asm volatile("cp.async.wait_group %0;" :: "n"(N) : "memory");
}
__device__ __forceinline__ void ldm_x4(uint32_t* r, uint32_t addr) {
    asm volatile("ldmatrix.sync.aligned.m8n8.x4.shared.b16 {%0,%1,%2,%3}, [%4];"
        : "=r"(r[0]), "=r"(r[1]), "=r"(r[2]), "=r"(r[3]) : "r"(addr));
}
__device__ __forceinline__ void ldm_x4_t(uint32_t* r, uint32_t addr) {
    asm volatile("ldmatrix.sync.aligned.m8n8.x4.trans.shared.b16 {%0,%1,%2,%3}, [%4];"
        : "=r"(r[0]), "=r"(r[1]), "=r"(r[2]), "=r"(r[3]) : "r"(addr));
}
__device__ __forceinline__ void mma_f16(float* c, const uint32_t* a, const uint32_t* b) {
    asm volatile(
        "mma.sync.aligned.m16n8k16.row.col.f32.f16.f16.f32 "
        "{%0,%1,%2,%3}, {%4,%5,%6,%7}, {%8,%9}, {%0,%1,%2,%3};"
        : "+f"(c[0]), "+f"(c[1]), "+f"(c[2]), "+f"(c[3])
        : "r"(a[0]), "r"(a[1]), "r"(a[2]), "r"(a[3]), "r"(b[0]), "r"(b[1]));
}
__device__ __forceinline__ uint32_t pack_h2(float x, float y) {
    __half2 h = __floats2half2_rn(x, y);
    return *(uint32_t*)&h;
}
__device__ __forceinline__ float ex2f(float x) {
    float r;
    asm("ex2.approx.f32 %0, %1;" : "=f"(r) : "f"(x));
    return r;
}

// ---------------------------------------------------------------------------
// FP16 tensor-core GEMM (R12/R14 config: 256 thr, 8 warps, 64x32 warp tile,
// 128x128 CTA tile, BK=64, 3 stages, 110 KB -> 2 CTA/SM).
// HALF_OUT=1: __half out + fused RMSNorm on q/k heads; q heads folded with
// log2e/sqrt(HD) (log2-domain softmax). HALF_OUT=0: float out.
// ---------------------------------------------------------------------------
#define BKG  64
#define GSTG 3
#define LDAH 72
#define ASTG_B (128 * LDAH * 2)
#define STG_B  (2 * ASTG_B)

template<int HALF_OUT>
__global__ __launch_bounds__(256) void gemm_mma(
    const __half* __restrict__ A, const __half* __restrict__ Bt,
    const float* __restrict__ bias, void* __restrict__ Cv,
    int N, int K,
    const float* __restrict__ q_scale, const float* __restrict__ k_scale)
{
    extern __shared__ __align__(16) char sh[];
    float* redf = (float*)sh;

    const int tid  = threadIdx.x;
    const int wid  = tid >> 5, lane = tid & 31;
    const int wm   = wid >> 2, wn = wid & 3;
    const int gid  = lane >> 2, tig = lane & 3;
    const int m0   = blockIdx.y * 128, n0 = blockIdx.x * 128;
    const int NC   = K / BKG;

    const uint32_t sBase = smem_u32(sh);

    const int a_row = (lane & 7) + ((lane >> 3) & 1) * 8;
    const int a_col = (lane >> 4) * 8;
    const int b_row = (lane & 7) + ((lane >> 4) & 1) * 8;
    const int b_col = ((lane >> 3) & 1) * 8;

    float acc[4][4][4];
    #pragma unroll
    for (int i = 0; i < 4; i++)
        #pragma unroll
        for (int j = 0; j < 4; j++)
            #pragma unroll
            for (int t = 0; t < 4; t++) acc[i][j][t] = 0.f;

    auto issue = [&](int c) {
        const int s = c % GSTG;
        const __half* Ag = A  + (size_t)m0 * K + c * BKG;
        const __half* Bg = Bt + (size_t)n0 * K + c * BKG;
        const uint32_t Ad = sBase + s * STG_B;
        const uint32_t Bd = Ad + ASTG_B;
        #pragma unroll
        for (int it = 0; it < 4; it++) {
            const int blk = tid + it * 256;
            const int row = blk >> 3, quad = blk & 7;
            cp16(Ad + (row * LDAH + quad * 8) * 2, Ag + (size_t)row * K + quad * 8);
            cp16(Bd + (row * LDAH + quad * 8) * 2, Bg + (size_t)row * K + quad * 8);
        }
        cp_commit();
    };

    issue(0);
    issue(1);

    for (int c = 0; c < NC; c++) {
        if (c + 1 >= NC) cp_wait<0>(); else cp_wait<1>();
        __syncthreads();
        if (c + 2 < NC) issue(c + 2);

        const int s = c % GSTG;
        const uint32_t Abase = sBase + s * STG_B + ((wm * 64 + a_row) * LDAH + a_col) * 2;
        const uint32_t Bbase = sBase + s * STG_B + ASTG_B + ((wn * 32 + b_row) * LDAH + b_col) * 2;

        #pragma unroll
        for (int k = 0; k < 4; k++) {
            uint32_t a[4][4], b[2][4];
            #pragma unroll
            for (int i = 0; i < 4; i++)
                ldm_x4(a[i], Abase + i * 16 * LDAH * 2 + k * 32);
            #pragma unroll
            for (int j2 = 0; j2 < 2; j2++)
                ldm_x4(b[j2], Bbase + j2 * 16 * LDAH * 2 + k * 32);
            #pragma unroll
            for (int i = 0; i < 4; i++) {
                #pragma unroll
                for (int j = 0; j < 4; j++)
                    mma_f16(acc[i][j], a[i], &b[j >> 1][(j & 1) * 2]);
            }
        }
    }

    #pragma unroll
    for (int j = 0; j < 4; j++) {
        const int col = n0 + wn * 32 + j * 8 + tig * 2;
        const float2 bz = *(const float2*)&bias[col];
        #pragma unroll
        for (int i = 0; i < 4; i++) {
            acc[i][j][0] += bz.x; acc[i][j][1] += bz.y;
            acc[i][j][2] += bz.x; acc[i][j][3] += bz.y;
        }
    }

    if (HALF_OUT) {
        __half* C = (__half*)Cv;
        float rlo[4], rhi[4];
        if (n0 < D_MODEL + KV_DIM) {
            __syncthreads();
            float sslo[4], sshi[4];
            #pragma unroll
            for (int i = 0; i < 4; i++) {
                float lo = 0.f, hi = 0.f;
                #pragma unroll
                for (int j = 0; j < 4; j++) {
                    lo += acc[i][j][0] * acc[i][j][0] + acc[i][j][1] * acc[i][j][1];
                    hi += acc[i][j][2] * acc[i][j][2] + acc[i][j][3] * acc[i][j][3];
                }
                lo += __shfl_xor_sync(0xffffffffu, lo, 1);
                lo += __shfl_xor_sync(0xffffffffu, lo, 2);
                hi += __shfl_xor_sync(0xffffffffu, hi, 1);
                hi += __shfl_xor_sync(0xffffffffu, hi, 2);
                sslo[i] = lo; sshi[i] = hi;
            }
            if (tig == 0) {
                #pragma unroll
                for (int i = 0; i < 4; i++) {
                    redf[(wm * 64 + i * 16 + gid) * 4 + wn]     = sslo[i];
                    redf[(wm * 64 + i * 16 + gid + 8) * 4 + wn] = sshi[i];
                }
            }
            __syncthreads();
            #pragma unroll
            for (int i = 0; i < 4; i++) {
                const int rl = wm * 64 + i * 16 + gid;
                const float s0 = redf[rl * 4] + redf[rl * 4 + 1] + redf[rl * 4 + 2] + redf[rl * 4 + 3];
                const float s1 = redf[(rl + 8) * 4] + redf[(rl + 8) * 4 + 1] + redf[(rl + 8) * 4 + 2] + redf[(rl + 8) * 4 + 3];
                rlo[i] = rsqrtf(s0 * (1.0f / HD) + 1e-6f);
                rhi[i] = rsqrtf(s1 * (1.0f / HD) + 1e-6f);
            }
        } else {
            #pragma unroll
            for (int i = 0; i < 4; i++) { rlo[i] = 1.f; rhi[i] = 1.f; }
        }
        const float* sc = (n0 < D_MODEL) ? q_scale : k_scale;
        // q heads folded with log2(e)/sqrt(HD): softmax runs in base-2 domain
        const float fold = (n0 < D_MODEL) ? 0.12751742f : 1.f;
        #pragma unroll
        for (int j = 0; j < 4; j++) {
            const int si = wn * 32 + j * 8 + tig * 2;
            const float sc0 = ((n0 < D_MODEL + KV_DIM) ? sc[si]     : 1.f) * fold;
            const float sc1 = ((n0 < D_MODEL + KV_DIM) ? sc[si + 1] : 1.f) * fold;
            const int col = n0 + si;
            #pragma unroll
            for (int i = 0; i < 4; i++) {
                const int r0 = m0 + wm * 64 + i * 16 + gid;
                *(uint32_t*)&C[(size_t)r0 * N + col] =
                    pack_h2(acc[i][j][0] * rlo[i] * sc0, acc[i][j][1] * rlo[i] * sc1);
                *(uint32_t*)&C[(size_t)(r0 + 8) * N + col] =
                    pack_h2(acc[i][j][2] * rhi[i] * sc0, acc[i][j][3] * rhi[i] * sc1);
            }
        }
    } else {
        float* C = (float*)Cv;
        #pragma unroll
        for (int j = 0; j < 4; j++) {
            const int col = n0 + wn * 32 + j * 8 + tig * 2;
            #pragma unroll
            for (int i = 0; i < 4; i++) {
                const int r0 = m0 + wm * 64 + i * 16 + gid;
                *(float2*)&C[(size_t)r0 * N + col]       = make_float2(acc[i][j][0], acc[i][j][1]);
                *(float2*)&C[(size_t)(r0 + 8) * N + col] = make_float2(acc[i][j][2], acc[i][j][3]);
            }
        }
    }
}

// ---------------------------------------------------------------------------
// Fused prep: segment 0 = cvt x -> fp16; segments 1/2 = transpose+convert W.
// ---------------------------------------------------------------------------
#define XBLK  (TOKENS * D_MODEL / (256 * 8))            // 8192
#define WQBLK ((QKVW / 32) * (KDIM / 32))               // 6144
#define WOBLK ((D_MODEL / 32) * (KDIM / 32))            // 4096

__global__ __launch_bounds__(256) void prep_all(
    const float* __restrict__ x,   __half* __restrict__ xc,
    const float* __restrict__ Wq,  __half* __restrict__ WqT,
    const float* __restrict__ Wo,  __half* __restrict__ WoT)
{
    __shared__ float t[32][33];
    const int b = blockIdx.x;
    if (b < XBLK) {
        const size_t i = ((size_t)b * 256 + threadIdx.x) * 8;
        const float4 v0 = *(const float4*)&x[i];
        const float4 v1 = *(const float4*)&x[i + 4];
        uint4 o;
        o.x = pack_h2(v0.x, v0.y); o.y = pack_h2(v0.z, v0.w);
        o.z = pack_h2(v1.x, v1.y); o.w = pack_h2(v1.z, v1.w);
        *(uint4*)&xc[i] = o;
        return;
    }
    const float* W; __half* Wt; int N, idx;
    if (b < XBLK + WQBLK) { W = Wq; Wt = WqT; N = QKVW;    idx = b - XBLK; }
    else                  { W = Wo; Wt = WoT; N = D_MODEL; idx = b - XBLK - WQBLK; }
    const int nb = (idx % (N / 32)) * 32, kb = (idx / (N / 32)) * 32;
    const int xq = threadIdx.x & 31, y4 = (threadIdx.x >> 5) * 4;
    #pragma unroll
    for (int i = 0; i < 4; i++) t[y4 + i][xq] = W[(size_t)(kb + y4 + i) * N + nb + xq];
    __syncthreads();
    #pragma unroll
    for (int i = 0; i < 4; i++)
        Wt[(size_t)(nb + y4 + i) * KDIM + kb + xq] = __float2half_rn(t[xq][y4 + i]);
}

// ---------------------------------------------------------------------------
// FP16 flash attention — 256 thr / 8 warps, P in registers, warp-local
// softmax in log2 domain (ex2), vote-gated rescale, final-diagonal skip.
// Double-buffered K/V; V^T via ldmatrix.trans. 1 barrier/tile.
// ---------------------------------------------------------------------------
#define QS_H 136
#define KS_H 136
#define KVB_B (64 * KS_H * 2)
#define FA_NT 256
#define FA_SMEM ((128*QS_H + 4*64*KS_H) * 2)

__global__ __launch_bounds__(FA_NT) void flash_attn_tc(
    const __half* __restrict__ qkv, __half* __restrict__ out)
{
    extern __shared__ __align__(16) char smc[];
    __half* Qs = (__half*)smc;                 // [128][136]
    __half* K0 = Qs + 128 * QS_H;              // [2][64][136]
    __half* V0 = K0 + 2 * 64 * KS_H;           // [2][64][136]

    const int qb = gridDim.x - 1 - blockIdx.x;
    const int h = blockIdx.y, n = blockIdx.z;
    const int kvh = h >> 2;
    const int q0 = qb * 128;
    const int tid = threadIdx.x, wid = tid >> 5, lane = tid & 31;
    const int gid = lane >> 2, tig = lane & 3;

    const __half* base = qkv + (size_t)n * SEQ * QKVW;
    const int qcol = h * HD;
    const int kcol = D_MODEL + kvh * HD;
    const int vcol = D_MODEL + KV_DIM + kvh * HD;

    const uint32_t sQ = smem_u32(Qs), sK0 = smem_u32(K0);
    const uint32_t sV0 = smem_u32(V0);

    const int ntiles = qb * 2 + 2;

    auto loadKV = [&](int t) {
        const int k0 = t * 64;
        const uint32_t off = (uint32_t)(t & 1) * KVB_B;
        #pragma unroll
        for (int it = 0; it < 4; it++) {
            const int i = (tid + it * FA_NT) * 8;
            const int r = i >> 7, c = i & 127;
            const size_t ro = (size_t)(k0 + r) * QKVW;
            cp16(sK0 + off + (r * KS_H + c) * 2, &base[ro + kcol + c]);
            cp16(sV0 + off + (r * KS_H + c) * 2, &base[ro + vcol + c]);
        }
        cp_commit();
    };

    loadKV(0);

    for (int i = tid * 8; i < 128 * HD; i += FA_NT * 8) {
        const int r = i >> 7, c = i & 127;
        *(uint4*)&Qs[r * QS_H + c] =
            *(const uint4*)&base[(size_t)(q0 + r) * QKVW + qcol + c];
    }

    const int a_row = (lane & 7) + ((lane >> 3) & 1) * 8;
    const int a_col = (lane >> 4) * 8;
    const int b_row = (lane & 7) + ((lane >> 4) & 1) * 8;
    const int b_col = ((lane >> 3) & 1) * 8;
    const int vt_row = (lane & 7) + ((lane >> 3) & 1) * 8;
    const int vt_col = (lane >> 4) * 8;

    const uint32_t QA = sQ + ((wid * 16 + a_row) * QS_H + a_col) * 2;
    const uint32_t KB = sK0 + (b_row * KS_H + b_col) * 2;
    const uint32_t VB = sV0 + (vt_row * KS_H + vt_col) * 2;

    float oacc[16][4];
    #pragma unroll
    for (int j = 0; j < 16; j++)
        #pragma unroll
        for (int t = 0; t < 4; t++) oacc[j][t] = 0.f;

    float m0 = -1e30f, m1 = -1e30f, l0 = 0.f, l1 = 0.f;
    const int row0 = q0 + wid * 16 + gid;
    const int row1 = row0 + 8;

    for (int t = 0; t < ntiles; t++) {
        const int k0 = t * 64;
        const uint32_t boff = (uint32_t)(t & 1) * KVB_B;
        cp_wait<0>();
        __syncthreads();   // KV(t) visible; buffer (t+1)&1 retired

        if (t + 1 < ntiles) loadKV(t + 1);

        // Final diagonal tile: bands 0-3 (rows < k0) are fully masked — skip.
        if (t == ntiles - 1 && wid < 4) continue;

        // S = Q @ K^T (scores in log2 domain; q pre-folded)
        float sacc[8][4];
        #pragma unroll
        for (int j = 0; j < 8; j++)
            #pragma unroll
            for (int tt = 0; tt < 4; tt++) sacc[j][tt] = 0.f;

        #pragma unroll
        for (int k = 0; k < 8; k++) {
            uint32_t a[4], b[4][4];
            ldm_x4(a, QA + k * 32);
            #pragma unroll
            for (int nt = 0; nt < 4; nt++)
                ldm_x4(b[nt], KB + boff + nt * 16 * KS_H * 2 + k * 32);
            #pragma unroll
            for (int j = 0; j < 8; j++)
                mma_f16(sacc[j], a, &b[j >> 1][(j & 1) * 2]);
        }

        // Causal mask (boundary tiles only) + warp-local row max
        float rm0 = -1e30f, rm1 = -1e30f;
        if (k0 + 64 > q0) {
            #pragma unroll
            for (int j = 0; j < 8; j++) {
                const int c0 = k0 + j * 8 + 2 * tig, c1 = c0 + 1;
                sacc[j][0] = (c0 <= row0) ? sacc[j][0] : -1e30f;
                sacc[j][1] = (c1 <= row0) ? sacc[j][1] : -1e30f;
                sacc[j][2] = (c0 <= row1) ? sacc[j][2] : -1e30f;
                sacc[j][3] = (c1 <= row1) ? sacc[j][3] : -1e30f;
                rm0 = fmaxf(rm0, fmaxf(sacc[j][0], sacc[j][1]));
                rm1 = fmaxf(rm1, fmaxf(sacc[j][2], sacc[j][3]));
            }
        } else {
            #pragma unroll
            for (int j = 0; j < 8; j++) {
                rm0 = fmaxf(rm0, fmaxf(sacc[j][0], sacc[j][1]));
                rm1 = fmaxf(rm1, fmaxf(sacc[j][2], sacc[j][3]));
            }
        }
        rm0 = fmaxf(rm0, __shfl_xor_sync(0xffffffffu, rm0, 1));
        rm0 = fmaxf(rm0, __shfl_xor_sync(0xffffffffu, rm0, 2));
        rm1 = fmaxf(rm1, __shfl_xor_sync(0xffffffffu, rm1, 1));
        rm1 = fmaxf(rm1, __shfl_xor_sync(0xffffffffu, rm1, 2));

        const bool noup = (rm0 <= m0) && (rm1 <= m1);
        uint32_t plo[8], phi[8];
        float ps0 = 0.f, ps1 = 0.f;

        if (__all_sync(0xffffffffu, noup)) {
            // max unchanged for all rows in warp: cor == 1, no rescale
            #pragma unroll
            for (int j = 0; j < 8; j++) {
                const float p00 = ex2f(sacc[j][0] - m0);
                const float p01 = ex2f(sacc[j][1] - m0);
                const float p10 = ex2f(sacc[j][2] - m1);
                const float p11 = ex2f(sacc[j][3] - m1);
                ps0 += p00 + p01; ps1 += p10 + p11;
                plo[j] = pack_h2(p00, p01);
                phi[j] = pack_h2(p10, p11);
            }
            ps0 += __shfl_xor_sync(0xffffffffu, ps0, 1);
            ps0 += __shfl_xor_sync(0xffffffffu, ps0, 2);
            ps1 += __shfl_xor_sync(0xffffffffu, ps1, 1);
            ps1 += __shfl_xor_sync(0xffffffffu, ps1, 2);
            l0 += ps0;
            l1 += ps1;
        } else {
            const float mn0 = fmaxf(m0, rm0), mn1 = fmaxf(m1, rm1);
            const float cor0 = ex2f(m0 - mn0), cor1 = ex2f(m1 - mn1);
            m0 = mn0; m1 = mn1;
            #pragma unroll
            for (int j = 0; j < 8; j++) {
                const float p00 = ex2f(sacc[j][0] - mn0);
                const float p01 = ex2f(sacc[j][1] - mn0);
                const float p10 = ex2f(sacc[j][2] - mn1);
                const float p11 = ex2f(sacc[j][3] - mn1);
                ps0 += p00 + p01; ps1 += p10 + p11;
                plo[j] = pack_h2(p00, p01);
                phi[j] = pack_h2(p10, p11);
            }
            ps0 += __shfl_xor_sync(0xffffffffu, ps0, 1);
            ps0 += __shfl_xor_sync(0xffffffffu, ps0, 2);
            ps1 += __shfl_xor_sync(0xffffffffu, ps1, 1);
            ps1 += __shfl_xor_sync(0xffffffffu, ps1, 2);
            l0 = l0 * cor0 + ps0;
            l1 = l1 * cor1 + ps1;
            #pragma unroll
            for (int j = 0; j < 16; j++) {
                oacc[j][0] *= cor0; oacc[j][1] *= cor0;
                oacc[j][2] *= cor1; oacc[j][3] *= cor1;
            }
        }

        // O += P @ V : P from registers
        #pragma unroll
        for (int kk = 0; kk < 4; kk++) {
            const uint32_t a[4] = { plo[2 * kk], phi[2 * kk],
                                    plo[2 * kk + 1], phi[2 * kk + 1] };
            #pragma unroll
            for (int nt = 0; nt < 8; nt++) {
                uint32_t b[4];
                ldm_x4_t(b, VB + boff + kk * 16 * KS_H * 2 + nt * 32);
                mma_f16(oacc[2 * nt],     a, &b[0]);
                mma_f16(oacc[2 * nt + 1], a, &b[2]);
            }
        }
    }

    // Epilogue: warp-local normalize + fp16 store
    const float i0 = 1.f / l0, i1 = 1.f / l1;
    __half* op0 = out + (size_t)(n * SEQ + row0) * D_MODEL + h * HD;
    __half* op1 = out + (size_t)(n * SEQ + row1) * D_MODEL + h * HD;
    #pragma unroll
    for (int j = 0; j < 16; j++) {
        const int c = j * 8 + 2 * tig;
        *(uint32_t*)&op0[c] = pack_h2(oacc[j][0] * i0, oacc[j][1] * i0);
        *(uint32_t*)&op1[c] = pack_h2(oacc[j][2] * i1, oacc[j][3] * i1);
    }
}

// ---------------------------------------------------------------------------
extern "C" void kernel_launch(void* const* d_in, const int* in_sizes, int n_in,
                              void* d_out, int out_size)
{
    const float* x       = (const float*)d_in[0];
    const float* Wqkv    = (const float*)d_in[1];
    const float* bqkv    = (const float*)d_in[2];
    const float* q_scale = (const float*)d_in[3];
    const float* k_scale = (const float*)d_in[4];
    const float* Wout    = (const float*)d_in[5];
    const float* bout    = (const float*)d_in[6];
    float* out = (float*)d_out;

    __half *qkv, *attn, *xc, *wqT, *woT;
    cudaGetSymbolAddress((void**)&qkv,  g_qkv);
    cudaGetSymbolAddress((void**)&attn, g_attn);
    cudaGetSymbolAddress((void**)&xc,   g_xc);
    cudaGetSymbolAddress((void**)&wqT,  g_wqkvT);
    cudaGetSymbolAddress((void**)&woT,  g_woutT);

    // Prep (single launch): cvt x + transpose/convert both weights
    prep_all<<<XBLK + WQBLK + WOBLK, 256>>>(x, xc, Wqkv, wqT, Wout, woT);

    const int gsmem = GSTG * STG_B;   // 110,592 B
    cudaFuncSetAttribute(gemm_mma<1>, cudaFuncAttributeMaxDynamicSharedMemorySize, gsmem);
    cudaFuncSetAttribute(gemm_mma<0>, cudaFuncAttributeMaxDynamicSharedMemorySize, gsmem);

    // 1) QKV projection + fused RMSNorm (q heads folded with log2e/sqrt(HD))
    gemm_mma<1><<<dim3(QKVW / 128, TOKENS / 128), 256, gsmem>>>(
        xc, wqT, bqkv, qkv, QKVW, KDIM, q_scale, k_scale);

    // 2) FP16 flash attention (log2-domain softmax, P in registers)
    cudaFuncSetAttribute(flash_attn_tc, cudaFuncAttributeMaxDynamicSharedMemorySize, FA_SMEM);
    flash_attn_tc<<<dim3(SEQ / 128, NH, NB), FA_NT, FA_SMEM>>>(qkv, attn);

    // 3) Output projection (fp32 out)
    gemm_mma<0><<<dim3(D_MODEL / 128, TOKENS / 128), 256, gsmem>>>(
        attn, woT, bout, out, D_MODEL, KDIM, nullptr, nullptr);
}

// round 17
// speedup vs baseline: 1.0400x; 1.0400x over previous
#include <cuda_runtime.h>
#include <cuda_fp16.h>
#include <math.h>
#include <stdint.h>

#define D_MODEL 2048
#define NH      16
#define NKV     4
#define HD      128
#define KV_DIM  512
#define QKVW    3072
#define NB      4
#define SEQ     2048
#define TOKENS  (NB * SEQ)
#define KDIM    2048

// Scratch (device globals — no runtime allocation)
__device__ __half g_qkv  [(size_t)TOKENS * QKVW];
__device__ __half g_attn [(size_t)TOKENS * D_MODEL];
__device__ __half g_xc   [(size_t)TOKENS * D_MODEL];
__device__ __half g_wqkvT[(size_t)QKVW   * D_MODEL];
__device__ __half g_woutT[(size_t)D_MODEL* D_MODEL];

// ---------------------------------------------------------------------------
// Helpers
// ---------------------------------------------------------------------------
__device__ __forceinline__ uint32_t smem_u32(const void* p) {
    uint32_t r;
    asm("{ .reg .u64 t; cvta.to.shared.u64 t, %1; cvt.u32.u64 %0, t; }" : "=r"(r) : "l"(p));
    return r;
}
__device__ __forceinline__ void cp16(uint32_t d, const void* s) {
    asm volatile("cp.async.cg.shared.global [%0], [%1], 16;" :: "r"(d), "l"(s));
}
__device__ __forceinline__ void cp_commit() {
    asm volatile("cp.async.commit_group;" ::: "memory");
}
template<int N> __device__ __forceinline__ void cp_wait() {
    asm volatile("cp.async.wait_group %0;" :: "n"(N) : "memory");
}
__device__ __forceinline__ void ldm_x4(uint32_t* r, uint32_t addr) {
    asm volatile("ldmatrix.sync.aligned.m8n8.x4.shared.b16 {%0,%1,%2,%3}, [%4];"
        : "=r"(r[0]), "=r"(r[1]), "=r"(r[2]), "=r"(r[3]) : "r"(addr));
}
__device__ __forceinline__ void ldm_x4_t(uint32_t* r, uint32_t addr) {
    asm volatile("ldmatrix.sync.aligned.m8n8.x4.trans.shared.b16 {%0,%1,%2,%3}, [%4];"
        : "=r"(r[0]), "=r"(r[1]), "=r"(r[2]), "=r"(r[3]) : "r"(addr));
}
__device__ __forceinline__ void mma_f16(float* c, const uint32_t* a, const uint32_t* b) {
    asm volatile(
        "mma.sync.aligned.m16n8k16.row.col.f32.f16.f16.f32 "
        "{%0,%1,%2,%3}, {%4,%5,%6,%7}, {%8,%9}, {%0,%1,%2,%3};"
        : "+f"(c[0]), "+f"(c[1]), "+f"(c[2]), "+f"(c[3])
        : "r"(a[0]), "r"(a[1]), "r"(a[2]), "r"(a[3]), "r"(b[0]), "r"(b[1]));
}
__device__ __forceinline__ uint32_t pack_h2(float x, float y) {
    __half2 h = __floats2half2_rn(x, y);
    return *(uint32_t*)&h;
}
__device__ __forceinline__ float ex2f(float x) {
    float r;
    asm("ex2.approx.f32 %0, %1;" : "=f"(r) : "f"(x));
    return r;
}

// ---------------------------------------------------------------------------
// FP16 tensor-core GEMM (R12/R14 config: 256 thr, 8 warps, 64x32 warp tile,
// 128x128 CTA tile, BK=64, 3 stages, 110 KB -> 2 CTA/SM).
// HALF_OUT=1: __half out + fused RMSNorm on q/k heads; q heads folded with
// log2e/sqrt(HD) (log2-domain softmax). HALF_OUT=0: float out.
// ---------------------------------------------------------------------------
#define BKG  64
#define GSTG 3
#define LDAH 72
#define ASTG_B (128 * LDAH * 2)
#define STG_B  (2 * ASTG_B)

template<int HALF_OUT>
__global__ __launch_bounds__(256) void gemm_mma(
    const __half* __restrict__ A, const __half* __restrict__ Bt,
    const float* __restrict__ bias, void* __restrict__ Cv,
    int N, int K,
    const float* __restrict__ q_scale, const float* __restrict__ k_scale)
{
    extern __shared__ __align__(16) char sh[];
    float* redf = (float*)sh;

    const int tid  = threadIdx.x;
    const int wid  = tid >> 5, lane = tid & 31;
    const int wm   = wid >> 2, wn = wid & 3;
    const int gid  = lane >> 2, tig = lane & 3;
    const int m0   = blockIdx.y * 128, n0 = blockIdx.x * 128;
    const int NC   = K / BKG;

    const uint32_t sBase = smem_u32(sh);

    const int a_row = (lane & 7) + ((lane >> 3) & 1) * 8;
    const int a_col = (lane >> 4) * 8;
    const int b_row = (lane & 7) + ((lane >> 4) & 1) * 8;
    const int b_col = ((lane >> 3) & 1) * 8;

    float acc[4][4][4];
    #pragma unroll
    for (int i = 0; i < 4; i++)
        #pragma unroll
        for (int j = 0; j < 4; j++)
            #pragma unroll
            for (int t = 0; t < 4; t++) acc[i][j][t] = 0.f;

    auto issue = [&](int c) {
        const int s = c % GSTG;
        const __half* Ag = A  + (size_t)m0 * K + c * BKG;
        const __half* Bg = Bt + (size_t)n0 * K + c * BKG;
        const uint32_t Ad = sBase + s * STG_B;
        const uint32_t Bd = Ad + ASTG_B;
        #pragma unroll
        for (int it = 0; it < 4; it++) {
            const int blk = tid + it * 256;
            const int row = blk >> 3, quad = blk & 7;
            cp16(Ad + (row * LDAH + quad * 8) * 2, Ag + (size_t)row * K + quad * 8);
            cp16(Bd + (row * LDAH + quad * 8) * 2, Bg + (size_t)row * K + quad * 8);
        }
        cp_commit();
    };

    issue(0);
    issue(1);

    for (int c = 0; c < NC; c++) {
        if (c + 1 >= NC) cp_wait<0>(); else cp_wait<1>();
        __syncthreads();
        if (c + 2 < NC) issue(c + 2);

        const int s = c % GSTG;
        const uint32_t Abase = sBase + s * STG_B + ((wm * 64 + a_row) * LDAH + a_col) * 2;
        const uint32_t Bbase = sBase + s * STG_B + ASTG_B + ((wn * 32 + b_row) * LDAH + b_col) * 2;

        #pragma unroll
        for (int k = 0; k < 4; k++) {
            uint32_t a[4][4], b[2][4];
            #pragma unroll
            for (int i = 0; i < 4; i++)
                ldm_x4(a[i], Abase + i * 16 * LDAH * 2 + k * 32);
            #pragma unroll
            for (int j2 = 0; j2 < 2; j2++)
                ldm_x4(b[j2], Bbase + j2 * 16 * LDAH * 2 + k * 32);
            #pragma unroll
            for (int i = 0; i < 4; i++) {
                #pragma unroll
                for (int j = 0; j < 4; j++)
                    mma_f16(acc[i][j], a[i], &b[j >> 1][(j & 1) * 2]);
            }
        }
    }

    #pragma unroll
    for (int j = 0; j < 4; j++) {
        const int col = n0 + wn * 32 + j * 8 + tig * 2;
        const float2 bz = *(const float2*)&bias[col];
        #pragma unroll
        for (int i = 0; i < 4; i++) {
            acc[i][j][0] += bz.x; acc[i][j][1] += bz.y;
            acc[i][j][2] += bz.x; acc[i][j][3] += bz.y;
        }
    }

    if (HALF_OUT) {
        __half* C = (__half*)Cv;
        float rlo[4], rhi[4];
        if (n0 < D_MODEL + KV_DIM) {
            __syncthreads();
            float sslo[4], sshi[4];
            #pragma unroll
            for (int i = 0; i < 4; i++) {
                float lo = 0.f, hi = 0.f;
                #pragma unroll
                for (int j = 0; j < 4; j++) {
                    lo += acc[i][j][0] * acc[i][j][0] + acc[i][j][1] * acc[i][j][1];
                    hi += acc[i][j][2] * acc[i][j][2] + acc[i][j][3] * acc[i][j][3];
                }
                lo += __shfl_xor_sync(0xffffffffu, lo, 1);
                lo += __shfl_xor_sync(0xffffffffu, lo, 2);
                hi += __shfl_xor_sync(0xffffffffu, hi, 1);
                hi += __shfl_xor_sync(0xffffffffu, hi, 2);
                sslo[i] = lo; sshi[i] = hi;
            }
            if (tig == 0) {
                #pragma unroll
                for (int i = 0; i < 4; i++) {
                    redf[(wm * 64 + i * 16 + gid) * 4 + wn]     = sslo[i];
                    redf[(wm * 64 + i * 16 + gid + 8) * 4 + wn] = sshi[i];
                }
            }
            __syncthreads();
            #pragma unroll
            for (int i = 0; i < 4; i++) {
                const int rl = wm * 64 + i * 16 + gid;
                const float s0 = redf[rl * 4] + redf[rl * 4 + 1] + redf[rl * 4 + 2] + redf[rl * 4 + 3];
                const float s1 = redf[(rl + 8) * 4] + redf[(rl + 8) * 4 + 1] + redf[(rl + 8) * 4 + 2] + redf[(rl + 8) * 4 + 3];
                rlo[i] = rsqrtf(s0 * (1.0f / HD) + 1e-6f);
                rhi[i] = rsqrtf(s1 * (1.0f / HD) + 1e-6f);
            }
        } else {
            #pragma unroll
            for (int i = 0; i < 4; i++) { rlo[i] = 1.f; rhi[i] = 1.f; }
        }
        const float* sc = (n0 < D_MODEL) ? q_scale : k_scale;
        // q heads folded with log2(e)/sqrt(HD): softmax runs in base-2 domain
        const float fold = (n0 < D_MODEL) ? 0.12751742f : 1.f;
        #pragma unroll
        for (int j = 0; j < 4; j++) {
            const int si = wn * 32 + j * 8 + tig * 2;
            const float sc0 = ((n0 < D_MODEL + KV_DIM) ? sc[si]     : 1.f) * fold;
            const float sc1 = ((n0 < D_MODEL + KV_DIM) ? sc[si + 1] : 1.f) * fold;
            const int col = n0 + si;
            #pragma unroll
            for (int i = 0; i < 4; i++) {
                const int r0 = m0 + wm * 64 + i * 16 + gid;
                *(uint32_t*)&C[(size_t)r0 * N + col] =
                    pack_h2(acc[i][j][0] * rlo[i] * sc0, acc[i][j][1] * rlo[i] * sc1);
                *(uint32_t*)&C[(size_t)(r0 + 8) * N + col] =
                    pack_h2(acc[i][j][2] * rhi[i] * sc0, acc[i][j][3] * rhi[i] * sc1);
            }
        }
    } else {
        float* C = (float*)Cv;
        #pragma unroll
        for (int j = 0; j < 4; j++) {
            const int col = n0 + wn * 32 + j * 8 + tig * 2;
            #pragma unroll
            for (int i = 0; i < 4; i++) {
                const int r0 = m0 + wm * 64 + i * 16 + gid;
                *(float2*)&C[(size_t)r0 * N + col]       = make_float2(acc[i][j][0], acc[i][j][1]);
                *(float2*)&C[(size_t)(r0 + 8) * N + col] = make_float2(acc[i][j][2], acc[i][j][3]);
            }
        }
    }
}

// ---------------------------------------------------------------------------
// Fused prep: segment 0 = cvt x -> fp16; segments 1/2 = transpose+convert W.
// ---------------------------------------------------------------------------
#define XBLK  (TOKENS * D_MODEL / (256 * 8))            // 8192
#define WQBLK ((QKVW / 32) * (KDIM / 32))               // 6144
#define WOBLK ((D_MODEL / 32) * (KDIM / 32))            // 4096

__global__ __launch_bounds__(256) void prep_all(
    const float* __restrict__ x,   __half* __restrict__ xc,
    const float* __restrict__ Wq,  __half* __restrict__ WqT,
    const float* __restrict__ Wo,  __half* __restrict__ WoT)
{
    __shared__ float t[32][33];
    const int b = blockIdx.x;
    if (b < XBLK) {
        const size_t i = ((size_t)b * 256 + threadIdx.x) * 8;
        const float4 v0 = *(const float4*)&x[i];
        const float4 v1 = *(const float4*)&x[i + 4];
        uint4 o;
        o.x = pack_h2(v0.x, v0.y); o.y = pack_h2(v0.z, v0.w);
        o.z = pack_h2(v1.x, v1.y); o.w = pack_h2(v1.z, v1.w);
        *(uint4*)&xc[i] = o;
        return;
    }
    const float* W; __half* Wt; int N, idx;
    if (b < XBLK + WQBLK) { W = Wq; Wt = WqT; N = QKVW;    idx = b - XBLK; }
    else                  { W = Wo; Wt = WoT; N = D_MODEL; idx = b - XBLK - WQBLK; }
    const int nb = (idx % (N / 32)) * 32, kb = (idx / (N / 32)) * 32;
    const int xq = threadIdx.x & 31, y4 = (threadIdx.x >> 5) * 4;
    #pragma unroll
    for (int i = 0; i < 4; i++) t[y4 + i][xq] = W[(size_t)(kb + y4 + i) * N + nb + xq];
    __syncthreads();
    #pragma unroll
    for (int i = 0; i < 4; i++)
        Wt[(size_t)(nb + y4 + i) * KDIM + kb + xq] = __float2half_rn(t[xq][y4 + i]);
}

// ---------------------------------------------------------------------------
// FP16 flash attention — 256 thr / 8 warps, P in registers, warp-local
// softmax in log2 domain (ex2, single path), final-diagonal skip.
// Double-buffered K/V; V^T via ldmatrix.trans. 1 barrier/tile.
// ---------------------------------------------------------------------------
#define QS_H 136
#define KS_H 136
#define KVB_B (64 * KS_H * 2)
#define FA_NT 256
#define FA_SMEM ((128*QS_H + 4*64*KS_H) * 2)

__global__ __launch_bounds__(FA_NT) void flash_attn_tc(
    const __half* __restrict__ qkv, __half* __restrict__ out)
{
    extern __shared__ __align__(16) char smc[];
    __half* Qs = (__half*)smc;                 // [128][136]
    __half* K0 = Qs + 128 * QS_H;              // [2][64][136]
    __half* V0 = K0 + 2 * 64 * KS_H;           // [2][64][136]

    const int qb = gridDim.x - 1 - blockIdx.x;
    const int h = blockIdx.y, n = blockIdx.z;
    const int kvh = h >> 2;
    const int q0 = qb * 128;
    const int tid = threadIdx.x, wid = tid >> 5, lane = tid & 31;
    const int gid = lane >> 2, tig = lane & 3;

    const __half* base = qkv + (size_t)n * SEQ * QKVW;
    const int qcol = h * HD;
    const int kcol = D_MODEL + kvh * HD;
    const int vcol = D_MODEL + KV_DIM + kvh * HD;

    const uint32_t sQ = smem_u32(Qs), sK0 = smem_u32(K0);
    const uint32_t sV0 = smem_u32(V0);

    const int ntiles = qb * 2 + 2;

    auto loadKV = [&](int t) {
        const int k0 = t * 64;
        const uint32_t off = (uint32_t)(t & 1) * KVB_B;
        #pragma unroll
        for (int it = 0; it < 4; it++) {
            const int i = (tid + it * FA_NT) * 8;
            const int r = i >> 7, c = i & 127;
            const size_t ro = (size_t)(k0 + r) * QKVW;
            cp16(sK0 + off + (r * KS_H + c) * 2, &base[ro + kcol + c]);
            cp16(sV0 + off + (r * KS_H + c) * 2, &base[ro + vcol + c]);
        }
        cp_commit();
    };

    loadKV(0);

    for (int i = tid * 8; i < 128 * HD; i += FA_NT * 8) {
        const int r = i >> 7, c = i & 127;
        *(uint4*)&Qs[r * QS_H + c] =
            *(const uint4*)&base[(size_t)(q0 + r) * QKVW + qcol + c];
    }

    const int a_row = (lane & 7) + ((lane >> 3) & 1) * 8;
    const int a_col = (lane >> 4) * 8;
    const int b_row = (lane & 7) + ((lane >> 4) & 1) * 8;
    const int b_col = ((lane >> 3) & 1) * 8;
    const int vt_row = (lane & 7) + ((lane >> 3) & 1) * 8;
    const int vt_col = (lane >> 4) * 8;

    const uint32_t QA = sQ + ((wid * 16 + a_row) * QS_H + a_col) * 2;
    const uint32_t KB = sK0 + (b_row * KS_H + b_col) * 2;
    const uint32_t VB = sV0 + (vt_row * KS_H + vt_col) * 2;

    float oacc[16][4];
    #pragma unroll
    for (int j = 0; j < 16; j++)
        #pragma unroll
        for (int t = 0; t < 4; t++) oacc[j][t] = 0.f;

    float m0 = -1e30f, m1 = -1e30f, l0 = 0.f, l1 = 0.f;
    const int row0 = q0 + wid * 16 + gid;
    const int row1 = row0 + 8;

    for (int t = 0; t < ntiles; t++) {
        const int k0 = t * 64;
        const uint32_t boff = (uint32_t)(t & 1) * KVB_B;
        cp_wait<0>();
        __syncthreads();   // KV(t) visible; buffer (t+1)&1 retired

        if (t + 1 < ntiles) loadKV(t + 1);

        // Final diagonal tile: bands 0-3 (rows < k0) fully masked — skip.
        if (t == ntiles - 1 && wid < 4) continue;

        // S = Q @ K^T (scores in log2 domain; q pre-folded)
        float sacc[8][4];
        #pragma unroll
        for (int j = 0; j < 8; j++)
            #pragma unroll
            for (int tt = 0; tt < 4; tt++) sacc[j][tt] = 0.f;

        #pragma unroll
        for (int k = 0; k < 8; k++) {
            uint32_t a[4], b[4][4];
            ldm_x4(a, QA + k * 32);
            #pragma unroll
            for (int nt = 0; nt < 4; nt++)
                ldm_x4(b[nt], KB + boff + nt * 16 * KS_H * 2 + k * 32);
            #pragma unroll
            for (int j = 0; j < 8; j++)
                mma_f16(sacc[j], a, &b[j >> 1][(j & 1) * 2]);
        }

        // Causal mask (boundary tiles only) + warp-local row max
        float rm0 = -1e30f, rm1 = -1e30f;
        if (k0 + 64 > q0) {
            #pragma unroll
            for (int j = 0; j < 8; j++) {
                const int c0 = k0 + j * 8 + 2 * tig, c1 = c0 + 1;
                sacc[j][0] = (c0 <= row0) ? sacc[j][0] : -1e30f;
                sacc[j][1] = (c1 <= row0) ? sacc[j][1] : -1e30f;
                sacc[j][2] = (c0 <= row1) ? sacc[j][2] : -1e30f;
                sacc[j][3] = (c1 <= row1) ? sacc[j][3] : -1e30f;
                rm0 = fmaxf(rm0, fmaxf(sacc[j][0], sacc[j][1]));
                rm1 = fmaxf(rm1, fmaxf(sacc[j][2], sacc[j][3]));
            }
        } else {
            #pragma unroll
            for (int j = 0; j < 8; j++) {
                rm0 = fmaxf(rm0, fmaxf(sacc[j][0], sacc[j][1]));
                rm1 = fmaxf(rm1, fmaxf(sacc[j][2], sacc[j][3]));
            }
        }
        rm0 = fmaxf(rm0, __shfl_xor_sync(0xffffffffu, rm0, 1));
        rm0 = fmaxf(rm0, __shfl_xor_sync(0xffffffffu, rm0, 2));
        rm1 = fmaxf(rm1, __shfl_xor_sync(0xffffffffu, rm1, 1));
        rm1 = fmaxf(rm1, __shfl_xor_sync(0xffffffffu, rm1, 2));

        const float mn0 = fmaxf(m0, rm0), mn1 = fmaxf(m1, rm1);
        const float cor0 = ex2f(m0 - mn0), cor1 = ex2f(m1 - mn1);
        m0 = mn0; m1 = mn1;

        // exp2 -> fp16 pairs kept in registers
        uint32_t plo[8], phi[8];
        float ps0 = 0.f, ps1 = 0.f;
        #pragma unroll
        for (int j = 0; j < 8; j++) {
            const float p00 = ex2f(sacc[j][0] - mn0);
            const float p01 = ex2f(sacc[j][1] - mn0);
            const float p10 = ex2f(sacc[j][2] - mn1);
            const float p11 = ex2f(sacc[j][3] - mn1);
            ps0 += p00 + p01; ps1 += p10 + p11;
            plo[j] = pack_h2(p00, p01);
            phi[j] = pack_h2(p10, p11);
        }
        ps0 += __shfl_xor_sync(0xffffffffu, ps0, 1);
        ps0 += __shfl_xor_sync(0xffffffffu, ps0, 2);
        ps1 += __shfl_xor_sync(0xffffffffu, ps1, 1);
        ps1 += __shfl_xor_sync(0xffffffffu, ps1, 2);
        l0 = l0 * cor0 + ps0;
        l1 = l1 * cor1 + ps1;

        #pragma unroll
        for (int j = 0; j < 16; j++) {
            oacc[j][0] *= cor0; oacc[j][1] *= cor0;
            oacc[j][2] *= cor1; oacc[j][3] *= cor1;
        }

        // O += P @ V : P from registers
        #pragma unroll
        for (int kk = 0; kk < 4; kk++) {
            const uint32_t a[4] = { plo[2 * kk], phi[2 * kk],
                                    plo[2 * kk + 1], phi[2 * kk + 1] };
            #pragma unroll
            for (int nt = 0; nt < 8; nt++) {
                uint32_t b[4];
                ldm_x4_t(b, VB + boff + kk * 16 * KS_H * 2 + nt * 32);
                mma_f16(oacc[2 * nt],     a, &b[0]);
                mma_f16(oacc[2 * nt + 1], a, &b[2]);
            }
        }
    }

    // Epilogue: warp-local normalize + fp16 store
    const float i0 = 1.f / l0, i1 = 1.f / l1;
    __half* op0 = out + (size_t)(n * SEQ + row0) * D_MODEL + h * HD;
    __half* op1 = out + (size_t)(n * SEQ + row1) * D_MODEL + h * HD;
    #pragma unroll
    for (int j = 0; j < 16; j++) {
        const int c = j * 8 + 2 * tig;
        *(uint32_t*)&op0[c] = pack_h2(oacc[j][0] * i0, oacc[j][1] * i0);
        *(uint32_t*)&op1[c] = pack_h2(oacc[j][2] * i1, oacc[j][3] * i1);
    }
}

// ---------------------------------------------------------------------------
extern "C" void kernel_launch(void* const* d_in, const int* in_sizes, int n_in,
                              void* d_out, int out_size)
{
    const float* x       = (const float*)d_in[0];
    const float* Wqkv    = (const float*)d_in[1];
    const float* bqkv    = (const float*)d_in[2];
    const float* q_scale = (const float*)d_in[3];
    const float* k_scale = (const float*)d_in[4];
    const float* Wout    = (const float*)d_in[5];
    const float* bout    = (const float*)d_in[6];
    float* out = (float*)d_out;

    __half *qkv, *attn, *xc, *wqT, *woT;
    cudaGetSymbolAddress((void**)&qkv,  g_qkv);
    cudaGetSymbolAddress((void**)&attn, g_attn);
    cudaGetSymbolAddress((void**)&xc,   g_xc);
    cudaGetSymbolAddress((void**)&wqT,  g_wqkvT);
    cudaGetSymbolAddress((void**)&woT,  g_woutT);

    // Prep (single launch): cvt x + transpose/convert both weights
    prep_all<<<XBLK + WQBLK + WOBLK, 256>>>(x, xc, Wqkv, wqT, Wout, woT);

    const int gsmem = GSTG * STG_B;   // 110,592 B
    cudaFuncSetAttribute(gemm_mma<1>, cudaFuncAttributeMaxDynamicSharedMemorySize, gsmem);
    cudaFuncSetAttribute(gemm_mma<0>, cudaFuncAttributeMaxDynamicSharedMemorySize, gsmem);

    // 1) QKV projection + fused RMSNorm (q heads folded with log2e/sqrt(HD))
    gemm_mma<1><<<dim3(QKVW / 128, TOKENS / 128), 256, gsmem>>>(
        xc, wqT, bqkv, qkv, QKVW, KDIM, q_scale, k_scale);

    // 2) FP16 flash attention (log2-domain softmax, P in registers)
    cudaFuncSetAttribute(flash_attn_tc, cudaFuncAttributeMaxDynamicSharedMemorySize, FA_SMEM);
    flash_attn_tc<<<dim3(SEQ / 128, NH, NB), FA_NT, FA_SMEM>>>(qkv, attn);

    // 3) Output projection (fp32 out)
    gemm_mma<0><<<dim3(D_MODEL / 128, TOKENS / 128), 256, gsmem>>>(
        attn, woT, bout, out, D_MODEL, KDIM, nullptr, nullptr);
}